// round 2
// baseline (speedup 1.0000x reference)
#include <cuda_runtime.h>
#include <math.h>

// Problem constants
#define S_   1000
#define B_   64
#define D_   440
#define H_   512
#define O_   1000
#define SB_  64000
#define H3_  1536

// ---------------- scratch (static __device__; no allocations allowed) ----------------
__device__ __align__(16) float g_Wcat[H3_ * D_];          // packed [Wh;Wz;Wr], row-major (1536 x 440)
__device__ __align__(16) float g_UzrT[H_ * 1024];         // UzrT[k*1024 + j]: j<512 -> Uz[j][k], else Ur[j-512][k]
__device__ __align__(16) float g_UhT[H_ * H_];            // UhT[k*512 + j] = Uh[j][k]
__device__ __align__(16) float g_Y[(size_t)SB_ * H3_];    // raw gate projections (pre-BN), rows = s*B+b
__device__ __align__(16) float g_Hst[(size_t)SB_ * H_];   // all hidden states h_t, row (t*B+b)
__device__ __align__(16) float g_zero[B_ * H_];           // h_{-1} = 0 (zero-initialized, never written)
__device__ float g_G1[H3_], g_B1[H3_];                    // packed gamma/beta for gate BN
__device__ float g_p1s[64 * H3_], g_p1q[64 * H3_];        // stats partials (deterministic 2-stage)
__device__ float g_A1[H3_], g_C1[H3_];                    // folded BN: y*A + C
__device__ float g_p2s[64 * O_], g_p2q[64 * O_];
__device__ float g_A2[O_], g_C2[O_];
__device__ __align__(16) float g_zrp[8][B_][1024];        // zr pre-activation partials (8 k-groups)
__device__ __align__(16) float g_hcp[16][B_][H_];         // hcand pre-activation partials (16 k-groups)
__device__ unsigned g_barCount;
__device__ volatile unsigned g_barEpoch;

// ---------------- grid barrier (all 128 CTAs resident on 148 SMs) ----------------
__device__ __forceinline__ void grid_barrier(unsigned nct) {
    __syncthreads();
    if (threadIdx.x == 0) {
        __threadfence();
        unsigned e = g_barEpoch;
        unsigned a = atomicAdd(&g_barCount, 1u);
        if (a == nct - 1u) {
            atomicExch(&g_barCount, 0u);
            __threadfence();
            g_barEpoch = e + 1u;
        } else {
            while (g_barEpoch == e) { }
            __threadfence();
        }
    }
    __syncthreads();
}

// ---------------- weight packing ----------------
__global__ void pack_w(const float* __restrict__ Wh, const float* __restrict__ Wz,
                       const float* __restrict__ Wr) {
    int i = blockIdx.x * 256 + threadIdx.x;          // < 1536*440 = 675840
    int j = i / D_, k = i - j * D_;
    float v = (j < 512) ? Wh[j * D_ + k] : (j < 1024) ? Wz[(j - 512) * D_ + k]
                                                      : Wr[(j - 1024) * D_ + k];
    g_Wcat[i] = v;
}

__global__ void pack_u(const float* __restrict__ Uh, const float* __restrict__ Uz,
                       const float* __restrict__ Ur) {
    int i = blockIdx.x * 256 + threadIdx.x;          // < 512*1024 + 512*512 = 786432
    if (i < H_ * 1024) {
        int k = i >> 10, j = i & 1023;
        g_UzrT[i] = (j < 512) ? Uz[j * H_ + k] : Ur[(j - 512) * H_ + k];
    } else {
        int i2 = i - H_ * 1024;
        int k = i2 >> 9, j = i2 & 511;
        g_UhT[i2] = Uh[j * H_ + k];
    }
}

__global__ void pack_gb(const float* __restrict__ gh, const float* __restrict__ bh,
                        const float* __restrict__ gz, const float* __restrict__ bz,
                        const float* __restrict__ gr, const float* __restrict__ br) {
    int i = blockIdx.x * 256 + threadIdx.x;          // < 1536
    float g, b;
    if (i < 512)      { g = gh[i];        b = bh[i]; }
    else if (i < 1024){ g = gz[i - 512];  b = bz[i - 512]; }
    else              { g = gr[i - 1024]; b = br[i - 1024]; }
    g_G1[i] = g; g_B1[i] = b;
}

// ---------------- fp32 SGEMM: C[M,N] = A[M,K] * Bw[N,K]^T ----------------
#define GBM 128
#define GBN 64
#define GBK 8
__global__ __launch_bounds__(256) void sgemm_kernel(
    const float* __restrict__ A, const float* __restrict__ Bw, float* __restrict__ C,
    int M, int N, int K, int ldc) {
    __shared__ float As[2][GBK][GBM + 4];
    __shared__ float Bs[2][GBK][GBN + 4];
    const int bm = blockIdx.y * GBM;
    const int bn = blockIdx.x * GBN;
    const int t  = threadIdx.x;
    const int tx = t & 15;            // 4 n-cols each
    const int ty = t >> 4;            // 8 m-rows each
    const int lam = t >> 1, lak = (t & 1) * 4;          // A loader: row, k-quad
    const int lbn = (t & 127) >> 1, lbk = (t & 1) * 4;  // B loader (threads < 128)
    const bool bload = t < 128;

    float acc[8][4];
#pragma unroll
    for (int i = 0; i < 8; i++)
#pragma unroll
        for (int j = 0; j < 4; j++) acc[i][j] = 0.f;

    const int nt = K / GBK;
    float4 va, vb;
    va = *(const float4*)(A + (size_t)(bm + lam) * K + lak);
    vb = make_float4(0.f, 0.f, 0.f, 0.f);
    if (bload && (bn + lbn) < N) vb = *(const float4*)(Bw + (size_t)(bn + lbn) * K + lbk);
    As[0][lak + 0][lam] = va.x; As[0][lak + 1][lam] = va.y;
    As[0][lak + 2][lam] = va.z; As[0][lak + 3][lam] = va.w;
    if (bload) {
        Bs[0][lbk + 0][lbn] = vb.x; Bs[0][lbk + 1][lbn] = vb.y;
        Bs[0][lbk + 2][lbn] = vb.z; Bs[0][lbk + 3][lbn] = vb.w;
    }
    __syncthreads();

    for (int kt = 0; kt < nt; kt++) {
        const int cur = kt & 1;
        const bool has = (kt + 1) < nt;
        if (has) {
            const int k0 = (kt + 1) * GBK;
            va = *(const float4*)(A + (size_t)(bm + lam) * K + k0 + lak);
            vb = make_float4(0.f, 0.f, 0.f, 0.f);
            if (bload && (bn + lbn) < N)
                vb = *(const float4*)(Bw + (size_t)(bn + lbn) * K + k0 + lbk);
        }
#pragma unroll
        for (int k = 0; k < GBK; k++) {
            float a[8], b[4];
#pragma unroll
            for (int i = 0; i < 8; i++) a[i] = As[cur][k][ty * 8 + i];
#pragma unroll
            for (int j = 0; j < 4; j++) b[j] = Bs[cur][k][tx * 4 + j];
#pragma unroll
            for (int i = 0; i < 8; i++)
#pragma unroll
                for (int j = 0; j < 4; j++)
                    acc[i][j] = fmaf(a[i], b[j], acc[i][j]);
        }
        if (has) {
            const int nb = cur ^ 1;
            As[nb][lak + 0][lam] = va.x; As[nb][lak + 1][lam] = va.y;
            As[nb][lak + 2][lam] = va.z; As[nb][lak + 3][lam] = va.w;
            if (bload) {
                Bs[nb][lbk + 0][lbn] = vb.x; Bs[nb][lbk + 1][lbn] = vb.y;
                Bs[nb][lbk + 2][lbn] = vb.z; Bs[nb][lbk + 3][lbn] = vb.w;
            }
        }
        __syncthreads();
    }

#pragma unroll
    for (int i = 0; i < 8; i++) {
        const size_t m = (size_t)(bm + ty * 8 + i);
#pragma unroll
        for (int j = 0; j < 4; j++) {
            const int n = bn + tx * 4 + j;
            if (n < N) C[m * ldc + n] = acc[i][j];
        }
    }
}

// ---------------- deterministic column stats (mean/var over 64000 rows) ----------------
__global__ void colstat_stage1(const float* __restrict__ X, int ncols,
                               float* __restrict__ ps, float* __restrict__ pq) {
    const int col = blockIdx.x * 256 + threadIdx.x;
    if (col >= ncols) return;
    const int chunk = blockIdx.y;                 // 64 chunks of 1000 rows
    const size_t base = (size_t)chunk * 1000 * ncols + col;
    float s = 0.f, q = 0.f;
    for (int r = 0; r < 1000; r++) {
        const float v = X[base + (size_t)r * ncols];
        s += v; q = fmaf(v, v, q);
    }
    ps[chunk * ncols + col] = s;
    pq[chunk * ncols + col] = q;
}

__global__ void colstat_stage2(const float* __restrict__ ps, const float* __restrict__ pq,
                               int ncols, const float* __restrict__ gamma,
                               const float* __restrict__ beta,
                               float* __restrict__ Aout, float* __restrict__ Cout) {
    const int col = blockIdx.x * 256 + threadIdx.x;
    if (col >= ncols) return;
    float s = 0.f, q = 0.f;
    for (int c = 0; c < 64; c++) { s += ps[c * ncols + col]; q += pq[c * ncols + col]; }
    const float m = s * (1.f / 64000.f);
    const float v = q * (1.f / 64000.f) - m * m;
    const float a = gamma[col] * rsqrtf(v + 1e-5f);
    Aout[col] = a;
    Cout[col] = beta[col] - m * a;
}

// ---------------- persistent GRU scan: 128 CTAs x 256 threads ----------------
__global__ __launch_bounds__(256, 1) void scan_kernel() {
    const int cta = blockIdx.x;        // 0..127
    const int tid = threadIdx.x;
    const int w = tid >> 5, lane = tid & 31;
    const int p1_jt = cta & 15, p1_kg = cta >> 4;   // 64 j / 64 k per CTA
    const int p2_jt = cta & 7,  p2_kg = cta >> 3;   // 64 j / 32 k per CTA
    __shared__ __align__(16) float s_rh[B_ * 32];

    for (int step = 0; step < S_; step++) {
        const float* h = step ? (g_Hst + (size_t)(step - 1) * (B_ * H_)) : g_zero;

        // ---- phase 1: zr_pre partial = h[b, kg] . UzrT[kg, j] ----
        {
            const int b0 = w * 8;
            const int j0 = p1_jt * 64 + lane;
            const int kbase = p1_kg * 64;
            float acc0[8], acc1[8];
#pragma unroll
            for (int i = 0; i < 8; i++) { acc0[i] = 0.f; acc1[i] = 0.f; }
            for (int kk = 0; kk < 64; kk += 4) {
                const int k = kbase + kk;
                float4 hb[8];
#pragma unroll
                for (int i = 0; i < 8; i++)
                    hb[i] = *(const float4*)(h + (b0 + i) * H_ + k);
#pragma unroll
                for (int q = 0; q < 4; q++) {
                    const float u0 = g_UzrT[(k + q) * 1024 + j0];
                    const float u1 = g_UzrT[(k + q) * 1024 + j0 + 32];
#pragma unroll
                    for (int i = 0; i < 8; i++) {
                        const float hv = (q == 0) ? hb[i].x : (q == 1) ? hb[i].y
                                        : (q == 2) ? hb[i].z : hb[i].w;
                        acc0[i] = fmaf(hv, u0, acc0[i]);
                        acc1[i] = fmaf(hv, u1, acc1[i]);
                    }
                }
            }
#pragma unroll
            for (int i = 0; i < 8; i++) {
                g_zrp[p1_kg][b0 + i][j0]      = acc0[i];
                g_zrp[p1_kg][b0 + i][j0 + 32] = acc1[i];
            }
        }
        grid_barrier(128);

        // ---- phase 2a: build rh[b, kc] slice for this CTA's 32-wide k-range ----
        {
            const int kb = p2_kg * 32;
#pragma unroll
            for (int ii = 0; ii < 8; ii++) {
                const int idx = tid + ii * 256;     // 0..2047 = 64 b x 32 kc
                const int b  = idx >> 5;
                const int kc = kb + (idx & 31);
                float pre = 0.f;
#pragma unroll
                for (int g = 0; g < 8; g++) pre += g_zrp[g][b][512 + kc];
                const size_t row = (size_t)step * B_ + b;
                const float wrn = g_Y[row * H3_ + 1024 + kc] * g_A1[1024 + kc] + g_C1[1024 + kc];
                const float r = 1.f / (1.f + expf(-(wrn + pre)));
                s_rh[idx] = r * h[b * H_ + kc];
            }
        }
        __syncthreads();

        // ---- phase 2b: hcand partial = rh[b, kg] . UhT[kg, j] ----
        {
            const int b0 = w * 8;
            const int j0 = p2_jt * 64 + lane;
            const int kb = p2_kg * 32;
            float acc0[8], acc1[8];
#pragma unroll
            for (int i = 0; i < 8; i++) { acc0[i] = 0.f; acc1[i] = 0.f; }
            for (int kk = 0; kk < 32; kk += 4) {
                float4 hb[8];
#pragma unroll
                for (int i = 0; i < 8; i++)
                    hb[i] = *(const float4*)(s_rh + (b0 + i) * 32 + kk);
#pragma unroll
                for (int q = 0; q < 4; q++) {
                    const float u0 = g_UhT[(kb + kk + q) * H_ + j0];
                    const float u1 = g_UhT[(kb + kk + q) * H_ + j0 + 32];
#pragma unroll
                    for (int i = 0; i < 8; i++) {
                        const float hv = (q == 0) ? hb[i].x : (q == 1) ? hb[i].y
                                        : (q == 2) ? hb[i].z : hb[i].w;
                        acc0[i] = fmaf(hv, u0, acc0[i]);
                        acc1[i] = fmaf(hv, u1, acc1[i]);
                    }
                }
            }
#pragma unroll
            for (int i = 0; i < 8; i++) {
                g_hcp[p2_kg][b0 + i][j0]      = acc0[i];
                g_hcp[p2_kg][b0 + i][j0 + 32] = acc1[i];
            }
        }
        grid_barrier(128);

        // ---- phase 3: combine -> h_t (32768 outputs, 1/thread) ----
        {
            const int gid = cta * 256 + tid;
            const int b = gid >> 9;
            const int j = gid & 511;
            float zpre = 0.f, hcpre = 0.f;
#pragma unroll
            for (int g = 0; g < 8; g++)  zpre  += g_zrp[g][b][j];
#pragma unroll
            for (int g = 0; g < 16; g++) hcpre += g_hcp[g][b][j];
            const size_t row = (size_t)step * B_ + b;
            const float wzn = g_Y[row * H3_ + 512 + j] * g_A1[512 + j] + g_C1[512 + j];
            const float whn = g_Y[row * H3_ + j] * g_A1[j] + g_C1[j];
            const float z  = 1.f / (1.f + expf(-(wzn + zpre)));
            const float hp = h[b * H_ + j];
            const float hc = tanhf(whn + hcpre);
            g_Hst[(size_t)step * (B_ * H_) + b * H_ + j] = z * hp + (1.f - z) * hc;
        }
        grid_barrier(128);
    }
}

// ---------------- row log_softmax with folded BN, in place on d_out ----------------
__global__ __launch_bounds__(256) void logsoftmax_kernel(float* __restrict__ C) {
    const int row = blockIdx.x;
    float* p = C + (size_t)row * O_;
    __shared__ float red[256];
    const int t = threadIdx.x;
    float mx = -3.4e38f;
    for (int j = t; j < O_; j += 256) {
        const float v = p[j] * g_A2[j] + g_C2[j];
        mx = fmaxf(mx, v);
    }
    red[t] = mx; __syncthreads();
    for (int s = 128; s > 0; s >>= 1) { if (t < s) red[t] = fmaxf(red[t], red[t + s]); __syncthreads(); }
    mx = red[0]; __syncthreads();
    float sum = 0.f;
    for (int j = t; j < O_; j += 256) {
        const float v = p[j] * g_A2[j] + g_C2[j];
        sum += expf(v - mx);
    }
    red[t] = sum; __syncthreads();
    for (int s = 128; s > 0; s >>= 1) { if (t < s) red[t] += red[t + s]; __syncthreads(); }
    const float lse = mx + logf(red[0]);
    __syncthreads();
    for (int j = t; j < O_; j += 256) {
        const float v = p[j] * g_A2[j] + g_C2[j];
        p[j] = v - lse;
    }
}

// ---------------- launch ----------------
extern "C" void kernel_launch(void* const* d_in, const int* in_sizes, int n_in,
                              void* d_out, int out_size) {
    const float* x  = (const float*)d_in[0];
    const float* Wh = (const float*)d_in[1];
    const float* Wz = (const float*)d_in[2];
    const float* Wr = (const float*)d_in[3];
    const float* Uh = (const float*)d_in[4];
    const float* Uz = (const float*)d_in[5];
    const float* Ur = (const float*)d_in[6];
    const float* gh = (const float*)d_in[7];
    const float* bh = (const float*)d_in[8];
    const float* gz = (const float*)d_in[9];
    const float* bz = (const float*)d_in[10];
    const float* gr = (const float*)d_in[11];
    const float* br = (const float*)d_in[12];
    const float* Wf = (const float*)d_in[13];
    const float* gf = (const float*)d_in[14];
    const float* bf = (const float*)d_in[15];
    float* out = (float*)d_out;

    float *pY, *pH, *pWcat, *p1s, *p1q, *p2s, *p2q, *pG1, *pB1, *pA1, *pC1, *pA2, *pC2;
    cudaGetSymbolAddress((void**)&pY,    g_Y);
    cudaGetSymbolAddress((void**)&pH,    g_Hst);
    cudaGetSymbolAddress((void**)&pWcat, g_Wcat);
    cudaGetSymbolAddress((void**)&p1s,   g_p1s);
    cudaGetSymbolAddress((void**)&p1q,   g_p1q);
    cudaGetSymbolAddress((void**)&p2s,   g_p2s);
    cudaGetSymbolAddress((void**)&p2q,   g_p2q);
    cudaGetSymbolAddress((void**)&pG1,   g_G1);
    cudaGetSymbolAddress((void**)&pB1,   g_B1);
    cudaGetSymbolAddress((void**)&pA1,   g_A1);
    cudaGetSymbolAddress((void**)&pC1,   g_C1);
    cudaGetSymbolAddress((void**)&pA2,   g_A2);
    cudaGetSymbolAddress((void**)&pC2,   g_C2);

    // 1) pack weights / transposed recurrent matrices / BN params
    pack_w <<<2640, 256>>>(Wh, Wz, Wr);
    pack_u <<<3072, 256>>>(Uh, Uz, Ur);
    pack_gb<<<6,    256>>>(gh, bh, gz, bz, gr, br);

    // 2) gate projections: Y[64000,1536] = x @ Wcat^T
    sgemm_kernel<<<dim3(H3_ / GBN, SB_ / GBM), 256>>>(x, pWcat, pY, SB_, H3_, D_, H3_);

    // 3) BN stats for gates (deterministic two-stage)
    colstat_stage1<<<dim3(6, 64), 256>>>(pY, H3_, p1s, p1q);
    colstat_stage2<<<6, 256>>>(p1s, p1q, H3_, pG1, pB1, pA1, pC1);

    // 4) persistent recurrent scan (1000 steps)
    scan_kernel<<<128, 256>>>();

    // 5) final projection into d_out: Ws_raw = H_all @ Wf^T
    sgemm_kernel<<<dim3((O_ + GBN - 1) / GBN, SB_ / GBM), 256>>>(pH, Wf, out, SB_, O_, H_, O_);

    // 6) BN stats for output + fold
    colstat_stage1<<<dim3(4, 64), 256>>>(out, O_, p2s, p2q);
    colstat_stage2<<<4, 256>>>(p2s, p2q, O_, gf, bf, pA2, pC2);

    // 7) BN-apply + log_softmax in place on d_out
    logsoftmax_kernel<<<SB_, 256>>>(out);
}